// round 15
// baseline (speedup 1.0000x reference)
#include <cuda_runtime.h>
#include <cuda_bf16.h>
#include <cstdint>

#define N_NODES 50000
#define N_EDGES 800000
#define IN_DIM  256
#define OUT_DIM 64
#define CAP     96          // bucket capacity per node (Poisson(16) tail: P(>96) ~ 0)

// ---- device-global scratch (allocation-free rule) ----
// g_count: zero at module load; re-zeroed by spmm_kernel every call.
__device__ float g_support[(size_t)N_NODES * OUT_DIM];   // 12.8 MB
__device__ int   g_count[N_NODES];                       // per-dst degree
__device__ int2  g_bucket[(size_t)N_NODES * CAP];        // 38.4 MB

// mma.sync m16n8k16 bf16 (sm_80+ plain feature — OK at .target sm_103)
__device__ __forceinline__ void mma_bf16(float* d, uint32_t a0, uint32_t a1,
                                         uint32_t a2, uint32_t a3,
                                         uint32_t b0, uint32_t b1) {
    asm volatile(
        "mma.sync.aligned.m16n8k16.row.col.f32.bf16.bf16.f32 "
        "{%0,%1,%2,%3}, {%4,%5,%6,%7}, {%8,%9}, {%0,%1,%2,%3};"
        : "+f"(d[0]), "+f"(d[1]), "+f"(d[2]), "+f"(d[3])
        : "r"(a0), "r"(a1), "r"(a2), "r"(a3), "r"(b0), "r"(b1));
}

// ---------------------------------------------------------------------------
// FUSED kernel: blocks [0, GEMM_BLOCKS) run the bf16 tensor GEMM tile
// (W split to bf16 hi/lo inline, vectorized); blocks [GEMM_BLOCKS, ...) run
// the bucket build (1 edge / thread). Independent work, co-resident.
// ---------------------------------------------------------------------------
#define TILE_M 128
#define KC     32
#define NCHUNK (IN_DIM / KC)    // 8
#define APAD   34               // bf16 per row (stride 17 words)
#define GEMM_BLOCKS ((N_NODES + TILE_M - 1) / TILE_M)          // 391
#define BUILD_BLOCKS ((N_EDGES + 255) / 256)                   // 3125
#define FUSED_BLOCKS (GEMM_BLOCKS + BUILD_BLOCKS)              // 3516

__device__ __forceinline__ void gemm_body(const float* __restrict__ X,
                                          const float* __restrict__ W, int blk) {
    __shared__ __nv_bfloat16 sAhi[TILE_M][APAD];
    __shared__ __nv_bfloat16 sAlo[TILE_M][APAD];
    __shared__ __nv_bfloat16 sBhi[OUT_DIM][APAD];
    __shared__ __nv_bfloat16 sBlo[OUT_DIM][APAD];

    const int tid  = threadIdx.x;
    const int wid  = tid >> 5;
    const int lane = tid & 31;
    const int gid  = lane >> 2;     // 0..7
    const int tig  = lane & 3;      // 0..3
    const int row0 = blk * TILE_M;

    float acc[8][4];
#pragma unroll
    for (int nt = 0; nt < 8; nt++)
#pragma unroll
        for (int q = 0; q < 4; q++) acc[nt][q] = 0.f;

    for (int ch = 0; ch < NCHUNK; ch++) {
        const int kc = ch * KC;
        // --- stage A chunk: 128 rows x 32 k, split to bf16 hi/lo ---
#pragma unroll
        for (int i = tid; i < TILE_M * (KC / 4); i += 256) {   // 1024 float4
            const int r = i >> 3;
            const int q = i & 7;
            const int grow = row0 + r;
            float4 x = make_float4(0.f, 0.f, 0.f, 0.f);
            if (grow < N_NODES)
                x = *reinterpret_cast<const float4*>(X + (size_t)grow * IN_DIM + kc + q * 4);
            __nv_bfloat162 h0 = make_bfloat162(__float2bfloat16_rn(x.x), __float2bfloat16_rn(x.y));
            __nv_bfloat162 h1 = make_bfloat162(__float2bfloat16_rn(x.z), __float2bfloat16_rn(x.w));
            __nv_bfloat162 l0 = make_bfloat162(
                __float2bfloat16_rn(x.x - __bfloat162float(h0.x)),
                __float2bfloat16_rn(x.y - __bfloat162float(h0.y)));
            __nv_bfloat162 l1 = make_bfloat162(
                __float2bfloat16_rn(x.z - __bfloat162float(h1.x)),
                __float2bfloat16_rn(x.w - __bfloat162float(h1.y)));
            *reinterpret_cast<__nv_bfloat162*>(&sAhi[r][q * 4])     = h0;
            *reinterpret_cast<__nv_bfloat162*>(&sAhi[r][q * 4 + 2]) = h1;
            *reinterpret_cast<__nv_bfloat162*>(&sAlo[r][q * 4])     = l0;
            *reinterpret_cast<__nv_bfloat162*>(&sAlo[r][q * 4 + 2]) = l1;
        }
        // --- stage B chunk: W[kc..kc+32][0..64] -> sB[n][k] bf16 hi/lo ---
        // float4 along n (coalesced); scattered 2B smem stores (transpose).
#pragma unroll
        for (int i = tid; i < KC * (OUT_DIM / 4); i += 256) {  // 512 float4
            const int k  = i >> 4;       // 0..31
            const int n4 = i & 15;       // float4 along n
            float4 w = *reinterpret_cast<const float4*>(W + (size_t)(kc + k) * OUT_DIM + n4 * 4);
            float wf[4] = {w.x, w.y, w.z, w.w};
#pragma unroll
            for (int j = 0; j < 4; j++) {
                __nv_bfloat16 hi = __float2bfloat16_rn(wf[j]);
                sBhi[n4 * 4 + j][k] = hi;
                sBlo[n4 * 4 + j][k] = __float2bfloat16_rn(wf[j] - __bfloat162float(hi));
            }
        }
        __syncthreads();

        const int ar = wid * 16 + gid;
#pragma unroll
        for (int ks = 0; ks < KC / 16; ks++) {
            const int k0w = ks * 8;
            uint32_t ahi0 = *reinterpret_cast<const uint32_t*>(&sAhi[ar][(k0w + tig) * 2]);
            uint32_t ahi1 = *reinterpret_cast<const uint32_t*>(&sAhi[ar + 8][(k0w + tig) * 2]);
            uint32_t ahi2 = *reinterpret_cast<const uint32_t*>(&sAhi[ar][(k0w + 4 + tig) * 2]);
            uint32_t ahi3 = *reinterpret_cast<const uint32_t*>(&sAhi[ar + 8][(k0w + 4 + tig) * 2]);
            uint32_t alo0 = *reinterpret_cast<const uint32_t*>(&sAlo[ar][(k0w + tig) * 2]);
            uint32_t alo1 = *reinterpret_cast<const uint32_t*>(&sAlo[ar + 8][(k0w + tig) * 2]);
            uint32_t alo2 = *reinterpret_cast<const uint32_t*>(&sAlo[ar][(k0w + 4 + tig) * 2]);
            uint32_t alo3 = *reinterpret_cast<const uint32_t*>(&sAlo[ar + 8][(k0w + 4 + tig) * 2]);
#pragma unroll
            for (int nt = 0; nt < 8; nt++) {
                const int br = nt * 8 + gid;
                uint32_t bh0 = *reinterpret_cast<const uint32_t*>(&sBhi[br][(k0w + tig) * 2]);
                uint32_t bh1 = *reinterpret_cast<const uint32_t*>(&sBhi[br][(k0w + 4 + tig) * 2]);
                uint32_t bl0 = *reinterpret_cast<const uint32_t*>(&sBlo[br][(k0w + tig) * 2]);
                uint32_t bl1 = *reinterpret_cast<const uint32_t*>(&sBlo[br][(k0w + 4 + tig) * 2]);
                mma_bf16(acc[nt], ahi0, ahi1, ahi2, ahi3, bh0, bh1);   // hi*hi
                mma_bf16(acc[nt], alo0, alo1, alo2, alo3, bh0, bh1);   // lo*hi
                mma_bf16(acc[nt], ahi0, ahi1, ahi2, ahi3, bl0, bl1);   // hi*lo
            }
        }
        __syncthreads();
    }

    const int r0 = row0 + wid * 16 + gid;
#pragma unroll
    for (int nt = 0; nt < 8; nt++) {
        const int col = nt * 8 + tig * 2;
        if (r0 < N_NODES)
            *reinterpret_cast<float2*>(g_support + (size_t)r0 * OUT_DIM + col) =
                make_float2(acc[nt][0], acc[nt][1]);
        if (r0 + 8 < N_NODES)
            *reinterpret_cast<float2*>(g_support + (size_t)(r0 + 8) * OUT_DIM + col) =
                make_float2(acc[nt][2], acc[nt][3]);
    }
}

__device__ __forceinline__ void build_body(const float* __restrict__ edge_val,
                                           const int* __restrict__ edge_src,
                                           const int* __restrict__ edge_dst, int blk) {
    int i = blk * 256 + threadIdx.x;
    if (i < N_EDGES) {
        int d = __ldg(&edge_dst[i]);
        int s = __ldg(&edge_src[i]);
        float v = __ldg(&edge_val[i]);
        int pos = atomicAdd(&g_count[d], 1);
        if (pos < CAP)
            g_bucket[(unsigned)d * CAP + (unsigned)pos] = make_int2(s, __float_as_int(v));
    }
}

__global__ __launch_bounds__(256) void fused_kernel(const float* __restrict__ X,
                                                    const float* __restrict__ W,
                                                    const float* __restrict__ edge_val,
                                                    const int* __restrict__ edge_src,
                                                    const int* __restrict__ edge_dst) {
    if (blockIdx.x < GEMM_BLOCKS)
        gemm_body(X, W, blockIdx.x);
    else
        build_body(edge_val, edge_src, edge_dst, blockIdx.x - GEMM_BLOCKS);
}

// ---------------------------------------------------------------------------
// Segmented SpMM over buckets: HALF-WARP per node, float4 per lane, two
// independent int2 bucket loads per iter, bias folded, no atomics, 32-bit
// indexing. Also re-zeros g_count for the next call (identical every call).
// ---------------------------------------------------------------------------
__global__ __launch_bounds__(256) void spmm_kernel(const float* __restrict__ bias,
                                                   float* __restrict__ out) {
    const int g = (blockIdx.x * 256 + threadIdx.x) >> 4;   // node id
    const int l = threadIdx.x & 15;                        // float4 lane
    if (g >= N_NODES) return;

    int cnt = g_count[g];
    if (l == 0) g_count[g] = 0;          // reset for next call
    if (cnt > CAP) cnt = CAP;
    const int2* bkt = g_bucket + (unsigned)g * CAP;

    float4 acc = reinterpret_cast<const float4*>(bias)[l];
    const float4* sup = reinterpret_cast<const float4*>(g_support);  // row = 16 float4

    int e = 0;
    for (; e + 1 < cnt; e += 2) {
        int2 p0 = bkt[e];
        int2 p1 = bkt[e + 1];
        float4 s0 = sup[(unsigned)p0.x * 16u + l];
        float4 s1 = sup[(unsigned)p1.x * 16u + l];
        float v0 = __int_as_float(p0.y);
        float v1 = __int_as_float(p1.y);
        acc.x = fmaf(v0, s0.x, acc.x); acc.y = fmaf(v0, s0.y, acc.y);
        acc.z = fmaf(v0, s0.z, acc.z); acc.w = fmaf(v0, s0.w, acc.w);
        acc.x = fmaf(v1, s1.x, acc.x); acc.y = fmaf(v1, s1.y, acc.y);
        acc.z = fmaf(v1, s1.z, acc.z); acc.w = fmaf(v1, s1.w, acc.w);
    }
    if (e < cnt) {
        int2 p = bkt[e];
        float4 s = sup[(unsigned)p.x * 16u + l];
        float v = __int_as_float(p.y);
        acc.x = fmaf(v, s.x, acc.x);
        acc.y = fmaf(v, s.y, acc.y);
        acc.z = fmaf(v, s.z, acc.z);
        acc.w = fmaf(v, s.w, acc.w);
    }

    reinterpret_cast<float4*>(out)[(unsigned)g * 16u + l] = acc;
}

// ---------------------------------------------------------------------------
extern "C" void kernel_launch(void* const* d_in, const int* in_sizes, int n_in,
                              void* d_out, int out_size) {
    const float* X    = (const float*)d_in[0];     // [50000, 256]
    const float* W    = (const float*)d_in[1];     // [256, 64]
    const float* bias = (const float*)d_in[2];     // [64]
    const float* ev   = (const float*)d_in[3];     // [800000]
    const int*   es   = (const int*)d_in[4];       // [800000] int32
    const int*   ed   = (const int*)d_in[5];       // [800000] int32
    float* out = (float*)d_out;                    // [50000, 64]

    // fused(gemm+build) -> spmm   (2 nodes)
    fused_kernel<<<FUSED_BLOCKS, 256>>>(X, W, ev, es, ed);
    spmm_kernel<<<(N_NODES * 16 + 255) / 256, 256>>>(bias, out);
}